// round 9
// baseline (speedup 1.0000x reference)
#include <cuda_runtime.h>
#include <math.h>
#include <float.h>

#define BATCH   256
#define NLEV    4
#define CDIM    8000
#define NTOTAL  10500
#define THREADS 512

// Packed accumulator: bits [0,48) fixed-point sum (x 2^32, all p >= 0),
// bits [48,..) arrival count. Integer adds commute exactly -> deterministic.
__device__ unsigned long long g_acc = 0ULL;

__device__ __forceinline__ void amax_comb(float& av, int& ai, float av2, int ai2) {
    if (av2 > av || (av2 == av && ai2 < ai)) { av = av2; ai = ai2; }
}

// FMA-pipe exp (no MUFU). Rel err <= ~5e-5; inputs clamped to >= -80.
__device__ __forceinline__ float fexp_poly(float x) {
    float t = fmaxf(x, -80.0f) * 1.4426950408889634f;
    float r = t + 12582912.0f;
    int   k = __float_as_int(r) - 0x4B400000;
    float f = t - (r - 12582912.0f);
    float p = 0.009618129107f;
    p = fmaf(p, f, 0.055504108664f);
    p = fmaf(p, f, 0.240226506959f);
    p = fmaf(p, f, 0.693147180560f);
    p = fmaf(p, f, 1.0f);
    return __int_as_float(__float_as_int(p) + (k << 23));
}

// Phase 1: issue all loads for one level into v[] (clamped addresses).
template<int N4, int STRIDE, int ITERS>
__device__ __forceinline__ void load_level(const float4* __restrict__ row4,
                                           int lt, float4* v) {
    #pragma unroll
    for (int k = 0; k < ITERS; k++) {
        int idx = lt + k * STRIDE;
        idx = (idx < N4) ? idx : (N4 - 1);
        v[k] = __ldg(&row4[idx]);
    }
}

// Phase 2: exp-sum + argmax + in-sweep target-logit extraction.
template<int N4, int STRIDE, int ITERS, bool NEED_SUM>
__device__ __forceinline__ void math_level(const float4* v, int lt, int tgt,
                                           volatile float* tlog_slot,
                                           float& s, float& av, int& ai) {
    const int tgt4 = tgt >> 2;
    const int tc   = tgt & 3;
    float s0 = 0.f, s1 = 0.f, s2 = 0.f, s3 = 0.f;
    float a0 = -FLT_MAX, a1 = -FLT_MAX, a2 = -FLT_MAX, a3 = -FLT_MAX;
    int   i0 = 0x7fffffff, i1 = 0x7fffffff, i2 = 0x7fffffff, i3 = 0x7fffffff;
    #pragma unroll
    for (int k = 0; k < ITERS; k++) {
        int  idx  = lt + k * STRIDE;
        bool pred = idx < N4;
        int  id   = pred ? idx : (N4 - 1);
        float4 w  = v[k];
        if (NEED_SUM && id == tgt4) {
            // Duplicate writers (clamped lanes) carry the same loaded value.
            float tv = (tc == 0) ? w.x : (tc == 1) ? w.y : (tc == 2) ? w.z : w.w;
            *tlog_slot = tv;
        }
        if (!pred) { w.x = w.y = w.z = w.w = -FLT_MAX; }
        int e = 4 * id;
        if (NEED_SUM) {
            if ((k & 1) == 0) {
                s0 += __expf(w.x); s1 += __expf(w.y);
                s2 += __expf(w.z); s3 += __expf(w.w);
            } else {
                s0 += fexp_poly(w.x); s1 += fexp_poly(w.y);
                s2 += fexp_poly(w.z); s3 += fexp_poly(w.w);
            }
        }
        if (w.x > a0) { a0 = w.x; i0 = e + 0; }
        if (w.y > a1) { a1 = w.y; i1 = e + 1; }
        if (w.z > a2) { a2 = w.z; i2 = e + 2; }
        if (w.w > a3) { a3 = w.w; i3 = e + 3; }
    }
    s = (s0 + s1) + (s2 + s3);
    av = a0; ai = i0;
    amax_comb(av, ai, a1, i1);
    amax_comb(av, ai, a2, i2);
    amax_comb(av, ai, a3, i3);
}

__global__ void __launch_bounds__(THREADS, 2) fused_taxanet_kernel(
    const float* __restrict__ y_pred,
    const int*   __restrict__ y_true,
    const float* __restrict__ H,
    float*       __restrict__ out)
{
    const int b    = blockIdx.x;
    const int tid  = threadIdx.x;
    const int warp = tid >> 5;
    const int lane = tid & 31;

    __shared__ float s_s[16], s_av[16];
    __shared__ int   s_ai[16];
    __shared__ int   s_tgt[4];
    __shared__ float s_tlogit[4];

    const float* base = y_pred + (size_t)b * NLEV * CDIM;

    // Segment mapping: warps [0,8)->L3, [8,12)->L2, [12,14)->L1, [14]->L0, [15]->y_true
    int j = 0, seg_base = 0;
    if (warp < 8)       { j = 3; seg_base = 0;  }
    else if (warp < 12) { j = 2; seg_base = 8;  }
    else if (warp < 14) { j = 1; seg_base = 12; }
    else if (warp < 15) { j = 0; seg_base = 14; }
    const int lt = tid - seg_base * 32;

    const float4* row4 = reinterpret_cast<const float4*>(base + (size_t)j * CDIM);

    // ---- Phase 1: issue loads / publish targets ----
    float4 v[8];
    if (warp == 15) {
        if (lane == 0) {
            int4 t = *reinterpret_cast<const int4*>(y_true + b * 4);
            s_tgt[1] = min(max(t.y, 0), 399);
            s_tgt[2] = min(max(t.z, 0), 1999);
            s_tgt[3] = min(max(t.w, 0), 7999);
            s_s[15] = 0.f; s_av[15] = -FLT_MAX; s_ai[15] = 0x7fffffff;
        }
    } else {
        if (j == 3)      load_level<2000, 256, 8>(row4, lt, v);
        else if (j == 2) load_level< 500, 128, 4>(row4, lt, v);
        else if (j == 1) load_level< 100,  64, 2>(row4, lt, v);
        else             load_level<  25,  32, 1>(row4, lt, v);
    }
    __syncthreads();   // publishes s_tgt; overlaps in-flight sweep loads

    // ---- Phase 2: math + warp reduce ----
    if (warp != 15) {
        const int tgt = (j > 0) ? s_tgt[j] : -4;   // -4: never matches
        float s, av; int ai;
        if (j == 3)      math_level<2000, 256, 8, true >(v, lt, tgt, &s_tlogit[3], s, av, ai);
        else if (j == 2) math_level< 500, 128, 4, true >(v, lt, tgt, &s_tlogit[2], s, av, ai);
        else if (j == 1) math_level< 100,  64, 2, true >(v, lt, tgt, &s_tlogit[1], s, av, ai);
        else             math_level<  25,  32, 1, false>(v, lt, tgt, &s_tlogit[0], s, av, ai);

        #pragma unroll
        for (int o = 16; o > 0; o >>= 1) {
            float s2  = __shfl_down_sync(0xffffffffu, s,  o);
            float av2 = __shfl_down_sync(0xffffffffu, av, o);
            int   ai2 = __shfl_down_sync(0xffffffffu, ai, o);
            s += s2;
            amax_comb(av, ai, av2, ai2);
        }
        if (lane == 0) { s_s[warp] = s; s_av[warp] = av; s_ai[warp] = ai; }
    }
    __syncthreads();

    // ---- Warp 0 tail: segmented reduce, H gathers, one packed atomic ----
    if (warp == 0) {
        float rs = 0.f, rav = -FLT_MAX; int rai = 0x7fffffff;
        if (lane < 16) { rs = s_s[lane]; rav = s_av[lane]; rai = s_ai[lane]; }
        const int segsz   = (lane < 8) ? 8 : (lane < 12) ? 4 : (lane < 14) ? 2 : 1;
        const int segbase = (lane < 8) ? 0 : (lane < 12) ? 8 : (lane < 14) ? 12 : 14;
        const int w = lane - segbase;
        #pragma unroll
        for (int o = 4; o > 0; o >>= 1) {
            float s2  = __shfl_down_sync(0xffffffffu, rs,  o);
            float av2 = __shfl_down_sync(0xffffffffu, rav, o);
            int   ai2 = __shfl_down_sync(0xffffffffu, rai, o);
            if (w + o < segsz) {
                rs += s2;
                amax_comb(rav, rai, av2, ai2);
            }
        }
        float nllv = 0.f;
        if (lane == 0)       nllv = __logf(rs) - s_tlogit[3];
        else if (lane == 8)  nllv = __logf(rs) - s_tlogit[2];
        else if (lane == 12) nllv = __logf(rs) - s_tlogit[1];

        const unsigned FULL = 0xffffffffu;
        int   g3i = __shfl_sync(FULL, rai, 0);
        int   g2i = __shfl_sync(FULL, rai, 8);
        int   g1i = __shfl_sync(FULL, rai, 12);
        int   g0i = __shfl_sync(FULL, rai, 14);
        float nll3 = __shfl_sync(FULL, nllv, 0);
        float nll2 = __shfl_sync(FULL, nllv, 8);
        float nll1 = __shfl_sync(FULL, nllv, 12);

        if (lane == 0) {
            const int g0 = g0i;
            const int g1 = g1i + 100;
            const int g2 = g2i + 500;
            const int g3 = g3i + 2500;

            float h01 = __ldg(&H[(size_t)g0 * NTOTAL + g1]);
            float h12 = __ldg(&H[(size_t)g1 * NTOTAL + g2]);
            float h23 = __ldg(&H[(size_t)g2 * NTOTAL + g3]);
            float c01 = (h01 == 1.0f) ? 1.0f : 0.0f;
            float c12 = (h12 == 1.0f) ? 1.0f : 0.0f;
            float c23 = (h23 == 1.0f) ? 1.0f : 0.0f;

            const float E    = 2.7182817459106445f;   // float32(np.e)
            const float invB = 1.0f / (float)BATCH;
            float p = 0.25f * (E * c01 + nll1 * invB)
                    + 0.15f * (E * c12 + nll2 * invB)
                    + 0.10f * (E * c23 + nll3 * invB);
            p = fmaxf(p, 0.0f);

            unsigned long long fx =
                (unsigned long long)__float2ll_rn(p * 4294967296.0f);
            unsigned long long old = atomicAdd(&g_acc, fx + (1ULL << 48));
            if ((old >> 48) == BATCH - 1) {
                unsigned long long tot = (old & 0xFFFFFFFFFFFFULL) + fx;
                out[0] = (float)((double)tot * (1.0 / 4294967296.0));
                g_acc = 0ULL;   // reset for graph replay
            }
        }
    }
}

extern "C" void kernel_launch(void* const* d_in, const int* in_sizes, int n_in,
                              void* d_out, int out_size) {
    const float* y_pred = (const float*)d_in[0];
    const int*   y_true = (const int*)d_in[1];
    const float* H      = (const float*)d_in[2];
    float*       out    = (float*)d_out;

    fused_taxanet_kernel<<<BATCH, THREADS>>>(y_pred, y_true, H, out);
}

// round 10
// speedup vs baseline: 1.0295x; 1.0295x over previous
#include <cuda_runtime.h>
#include <math.h>
#include <float.h>

#define BATCH   256
#define NLEV    4
#define CDIM    8000
#define NTOTAL  10500
#define THREADS 512
#define FLAT_N  2625          // total valid float4s: 2000+500+100+25
#define SWEEPT  480           // 15 sweep warps

// Packed accumulator: bits [0,48) fixed-point sum (x 2^32, all p >= 0),
// bits [48,..) arrival count. Integer adds commute exactly -> deterministic.
__device__ unsigned long long g_acc = 0ULL;

__device__ __forceinline__ void amax_comb(float& av, int& ai, float av2, int ai2) {
    if (av2 > av || (av2 == av && ai2 < ai)) { av = av2; ai = ai2; }
}

__device__ __forceinline__ void acc4(float4 w, int e, float& s, float& av, int& ai) {
    s += __expf(w.x); if (w.x > av) { av = w.x; ai = e + 0; }
    s += __expf(w.y); if (w.y > av) { av = w.y; ai = e + 1; }
    s += __expf(w.z); if (w.z > av) { av = w.z; ai = e + 2; }
    s += __expf(w.w); if (w.w > av) { av = w.w; ai = e + 3; }
}

__device__ __forceinline__ void wred(float& s, float& av, int& ai) {
    #pragma unroll
    for (int o = 16; o > 0; o >>= 1) {
        float s2  = __shfl_down_sync(0xffffffffu, s,  o);
        float av2 = __shfl_down_sync(0xffffffffu, av, o);
        int   ai2 = __shfl_down_sync(0xffffffffu, ai, o);
        s += s2;
        amax_comb(av, ai, av2, ai2);
    }
}

__global__ void __launch_bounds__(THREADS, 2) fused_taxanet_kernel(
    const float* __restrict__ y_pred,
    const int*   __restrict__ y_true,
    const float* __restrict__ H,
    float*       __restrict__ out)
{
    const int b    = blockIdx.x;
    const int tid  = threadIdx.x;
    const int warp = tid >> 5;
    const int lane = tid & 31;

    __shared__ float s_s[4][16], s_av[4][16];
    __shared__ int   s_ai[4][16];
    __shared__ float s_tlogit[4];

    const float*  base = y_pred + (size_t)b * NLEV * CDIM;
    const float4* b4   = reinterpret_cast<const float4*>(base);

    if (warp == 15) {
        // Prefetch target logits (two trips, fully overlapped with the sweep).
        if (lane < 3) {
            const int jj  = lane + 1;
            const int szs = (jj == 1) ? 400 : (jj == 2) ? 2000 : 8000;
            int tgt = __ldg(&y_true[b * NLEV + jj]);
            tgt = min(max(tgt, 0), szs - 1);
            s_tlogit[jj] = __ldg(base + (size_t)jj * CDIM + tgt);
        }
        if (lane < 4) { s_s[lane][15] = 0.f; s_av[lane][15] = -FLT_MAX; s_ai[lane][15] = 0x7fffffff; }
    } else {
        // ---- Flat balanced sweep: 6 float4s per thread over all levels ----
        float4 v[6]; int e4[6], lv[6]; bool p[6];
        #pragma unroll
        for (int k = 0; k < 6; k++) {
            int fi = tid + k * SWEEPT;
            p[k] = fi < FLAT_N;
            fi = p[k] ? fi : (FLAT_N - 1);
            int l, e, a4;
            if (fi < 2000)      { l = 3; e = fi;        a4 = 6000 + e; }
            else if (fi < 2500) { l = 2; e = fi - 2000; a4 = 4000 + e; }
            else if (fi < 2600) { l = 1; e = fi - 2500; a4 = 2000 + e; }
            else                { l = 0; e = fi - 2600; a4 = e; }
            lv[k] = l; e4[k] = e;
            v[k] = __ldg(b4 + a4);        // all 6 loads issued up-front
        }

        float s3 = 0.f, s2 = 0.f, s1 = 0.f;
        float av3 = -FLT_MAX, av2 = -FLT_MAX, av1 = -FLT_MAX, av0 = -FLT_MAX;
        int   ai3 = 0x7fffffff, ai2 = 0x7fffffff, ai1 = 0x7fffffff, ai0 = 0x7fffffff;

        #pragma unroll
        for (int k = 0; k < 6; k++) {
            float4 w = v[k];
            if (!p[k]) { w.x = w.y = w.z = w.w = -FLT_MAX; }   // exp->0, never argmax
            int e = 4 * e4[k];
            if (lv[k] == 3)      acc4(w, e, s3, av3, ai3);
            else if (lv[k] == 2) acc4(w, e, s2, av2, ai2);
            else if (lv[k] == 1) acc4(w, e, s1, av1, ai1);
            else {
                // L0: argmax only (ce[0] unused)
                if (w.x > av0) { av0 = w.x; ai0 = e + 0; }
                if (w.y > av0) { av0 = w.y; ai0 = e + 1; }
                if (w.z > av0) { av0 = w.z; ai0 = e + 2; }
                if (w.w > av0) { av0 = w.w; ai0 = e + 3; }
            }
        }

        float s0d = 0.f;
        wred(s3, av3, ai3);
        wred(s2, av2, ai2);
        wred(s1, av1, ai1);
        wred(s0d, av0, ai0);
        if (lane == 0) {
            s_s[3][warp] = s3;  s_av[3][warp] = av3; s_ai[3][warp] = ai3;
            s_s[2][warp] = s2;  s_av[2][warp] = av2; s_ai[2][warp] = ai2;
            s_s[1][warp] = s1;  s_av[1][warp] = av1; s_ai[1][warp] = ai1;
            s_s[0][warp] = 0.f; s_av[0][warp] = av0; s_ai[0][warp] = ai0;
        }
    }
    __syncthreads();   // the ONLY block-wide barrier

    // ---- Warp 0: fold 16x4 partials, H gathers, one packed atomic ----
    if (warp == 0) {
        const int lev = lane >> 3;          // 0..3
        const int i   = lane & 7;           // 0..7
        float rs  = s_s[lev][i] + s_s[lev][i + 8];       // fixed pair order
        float rav = s_av[lev][i];
        int   rai = s_ai[lev][i];
        amax_comb(rav, rai, s_av[lev][i + 8], s_ai[lev][i + 8]);
        #pragma unroll
        for (int o = 4; o > 0; o >>= 1) {
            float s2  = __shfl_down_sync(0xffffffffu, rs,  o);
            float av2 = __shfl_down_sync(0xffffffffu, rav, o);
            int   ai2 = __shfl_down_sync(0xffffffffu, rai, o);
            if (i + o < 8) {
                rs += s2;
                amax_comb(rav, rai, av2, ai2);
            }
        }
        // Segment heads at lanes 0(L0), 8(L1), 16(L2), 24(L3).
        float nllv = 0.f;
        if (i == 0 && lev > 0) nllv = __logf(rs) - s_tlogit[lev];

        const unsigned FULL = 0xffffffffu;
        int   g0i  = __shfl_sync(FULL, rai,  0);
        int   g1i  = __shfl_sync(FULL, rai,  8);
        int   g2i  = __shfl_sync(FULL, rai, 16);
        int   g3i  = __shfl_sync(FULL, rai, 24);
        float nll1 = __shfl_sync(FULL, nllv,  8);
        float nll2 = __shfl_sync(FULL, nllv, 16);
        float nll3 = __shfl_sync(FULL, nllv, 24);

        if (lane == 0) {
            const int g0 = g0i;
            const int g1 = g1i + 100;
            const int g2 = g2i + 500;
            const int g3 = g3i + 2500;

            float h01 = __ldg(&H[(size_t)g0 * NTOTAL + g1]);
            float h12 = __ldg(&H[(size_t)g1 * NTOTAL + g2]);
            float h23 = __ldg(&H[(size_t)g2 * NTOTAL + g3]);
            float c01 = (h01 == 1.0f) ? 1.0f : 0.0f;
            float c12 = (h12 == 1.0f) ? 1.0f : 0.0f;
            float c23 = (h23 == 1.0f) ? 1.0f : 0.0f;

            const float E    = 2.7182817459106445f;   // float32(np.e)
            const float invB = 1.0f / (float)BATCH;
            float p = 0.25f * (E * c01 + nll1 * invB)
                    + 0.15f * (E * c12 + nll2 * invB)
                    + 0.10f * (E * c23 + nll3 * invB);
            p = fmaxf(p, 0.0f);   // mathematically guaranteed; guards fixed-point

            unsigned long long fx =
                (unsigned long long)__float2ll_rn(p * 4294967296.0f);   // * 2^32
            unsigned long long old = atomicAdd(&g_acc, fx + (1ULL << 48));
            if ((old >> 48) == BATCH - 1) {
                unsigned long long tot = (old & 0xFFFFFFFFFFFFULL) + fx;
                out[0] = (float)((double)tot * (1.0 / 4294967296.0));
                g_acc = 0ULL;   // reset for graph replay
            }
        }
    }
}

extern "C" void kernel_launch(void* const* d_in, const int* in_sizes, int n_in,
                              void* d_out, int out_size) {
    const float* y_pred = (const float*)d_in[0];
    const int*   y_true = (const int*)d_in[1];
    const float* H      = (const float*)d_in[2];
    float*       out    = (float*)d_out;

    fused_taxanet_kernel<<<BATCH, THREADS>>>(y_pred, y_true, H, out);
}